// round 2
// baseline (speedup 1.0000x reference)
#include <cuda_runtime.h>

// 2-qubit dense gate on 24-qubit state, batch=4 (innermost, contiguous).
// Flat float index = qindex * 4 + b.  qubit k -> bit (23-k) of qindex.
// support (5,12) -> qindex bits 18 and 11.
//
// R2: 2 rest-indices per thread (interleaved) -> 8 independent LDG.128 +
// 8 STG.128 per thread for higher per-warp MLP; streaming cache hints
// (__ldcs/__stcs) since every byte is touched exactly once.

static constexpr unsigned REST_BITS = 22;          // 24 - 2 support qubits
static constexpr unsigned N_REST    = 1u << REST_BITS;
static constexpr unsigned BIT_C     = 1u << 18;    // qubit 5
static constexpr unsigned BIT_D     = 1u << 11;    // qubit 12

__device__ __forceinline__ unsigned expand_rest(unsigned r)
{
    unsigned low = r & 0x7FFu;           // bits 0..10
    unsigned mid = (r >> 11) & 0x3Fu;    // -> qindex bits 12..17
    unsigned hi  = r >> 17;              // -> qindex bits 19..23
    return low | (mid << 12) | (hi << 19);
}

__global__ void __launch_bounds__(256)
quantum_gate2_kernel(const float4* __restrict__ in,
                     const float*  __restrict__ gate,
                     float4*       __restrict__ out)
{
    unsigned t  = blockIdx.x * blockDim.x + threadIdx.x;
    unsigned q0 = expand_rest(2u * t);
    unsigned q1 = expand_rest(2u * t + 1u);

    // Front-batch all 8 loads (MLP=8), streaming (evict-first).
    float4 a0 = __ldcs(&in[q0]);
    float4 a1 = __ldcs(&in[q0 | BIT_D]);
    float4 a2 = __ldcs(&in[q0 | BIT_C]);
    float4 a3 = __ldcs(&in[q0 | BIT_C | BIT_D]);
    float4 b0 = __ldcs(&in[q1]);
    float4 b1 = __ldcs(&in[q1 | BIT_D]);
    float4 b2 = __ldcs(&in[q1 | BIT_C]);
    float4 b3 = __ldcs(&in[q1 | BIT_C | BIT_D]);

    // Gate: 16 floats, uniform broadcast (L1-resident).
    float g[16];
#pragma unroll
    for (int i = 0; i < 16; i++) g[i] = __ldg(gate + i);

    float4 oa[4], ob[4];
#pragma unroll
    for (int i = 0; i < 4; i++) {
        const float g0 = g[4*i+0], g1 = g[4*i+1], g2 = g[4*i+2], g3 = g[4*i+3];
        oa[i].x = g0*a0.x + g1*a1.x + g2*a2.x + g3*a3.x;
        oa[i].y = g0*a0.y + g1*a1.y + g2*a2.y + g3*a3.y;
        oa[i].z = g0*a0.z + g1*a1.z + g2*a2.z + g3*a3.z;
        oa[i].w = g0*a0.w + g1*a1.w + g2*a2.w + g3*a3.w;
        ob[i].x = g0*b0.x + g1*b1.x + g2*b2.x + g3*b3.x;
        ob[i].y = g0*b0.y + g1*b1.y + g2*b2.y + g3*b3.y;
        ob[i].z = g0*b0.z + g1*b1.z + g2*b2.z + g3*b3.z;
        ob[i].w = g0*b0.w + g1*b1.w + g2*b2.w + g3*b3.w;
    }

    __stcs(&out[q0],                 oa[0]);
    __stcs(&out[q1],                 ob[0]);
    __stcs(&out[q0 | BIT_D],         oa[1]);
    __stcs(&out[q1 | BIT_D],         ob[1]);
    __stcs(&out[q0 | BIT_C],         oa[2]);
    __stcs(&out[q1 | BIT_C],         ob[2]);
    __stcs(&out[q0 | BIT_C | BIT_D], oa[3]);
    __stcs(&out[q1 | BIT_C | BIT_D], ob[3]);
}

extern "C" void kernel_launch(void* const* d_in, const int* in_sizes, int n_in,
                              void* d_out, int out_size)
{
    const float4* state = (const float4*)d_in[0];
    const float*  gate  = (const float*)d_in[1];
    float4*       out   = (float4*)d_out;

    const unsigned threads = 256;
    const unsigned blocks  = (N_REST / 2) / threads;   // 2^21 / 256 = 8192
    quantum_gate2_kernel<<<blocks, threads>>>(state, gate, out);
}

// round 5
// speedup vs baseline: 1.0268x; 1.0268x over previous
#include <cuda_runtime.h>

// 2-qubit dense gate on 24-qubit state, batch=4 (innermost, contiguous).
// Flat float index = qindex * 4 + b.  qubit k -> bit (23-k) of qindex.
// support (5,12) -> qindex bits 18 and 11.
//
// R5 (retry of R3/R4 after two container-level infra failures):
// 1 rest-index/thread, gate in shared memory (LDS broadcast, removes
// 16 LDG/thread from the live set), store-as-computed (4 live
// accumulators), __launch_bounds__(256,8) caps regs at 32 for max
// occupancy. Streaming stores — every byte is touched exactly once.

static constexpr unsigned REST_BITS = 22;          // 24 - 2 support qubits
static constexpr unsigned N_REST    = 1u << REST_BITS;
static constexpr unsigned BIT_C     = 1u << 18;    // qubit 5
static constexpr unsigned BIT_D     = 1u << 11;    // qubit 12

__global__ void __launch_bounds__(256, 8)
quantum_gate2_kernel(const float4* __restrict__ in,
                     const float*  __restrict__ gate,
                     float4*       __restrict__ out)
{
    __shared__ float gs[16];
    if (threadIdx.x < 16) gs[threadIdx.x] = gate[threadIdx.x];
    __syncthreads();

    const unsigned r = blockIdx.x * blockDim.x + threadIdx.x;
    // Expand rest index: insert zero bits at qindex positions 11 and 18.
    const unsigned low = r & 0x7FFu;           // bits 0..10
    const unsigned mid = (r >> 11) & 0x3Fu;    // -> qindex bits 12..17
    const unsigned hi  = r >> 17;              // -> qindex bits 19..23
    const unsigned qb  = low | (mid << 12) | (hi << 19);

    const float4* pin  = in  + qb;
    float4*       pout = out + qb;

    // Front-batch the 4 independent 16B loads (per-thread MLP=4).
    const float4 v0 = pin[0u];                // c=0,d=0
    const float4 v1 = pin[BIT_D];             // c=0,d=1
    const float4 v2 = pin[BIT_C];             // c=1,d=0
    const float4 v3 = pin[BIT_C + BIT_D];     // c=1,d=1

    float4 o;

    o.x = gs[0]*v0.x + gs[1]*v1.x + gs[2]*v2.x + gs[3]*v3.x;
    o.y = gs[0]*v0.y + gs[1]*v1.y + gs[2]*v2.y + gs[3]*v3.y;
    o.z = gs[0]*v0.z + gs[1]*v1.z + gs[2]*v2.z + gs[3]*v3.z;
    o.w = gs[0]*v0.w + gs[1]*v1.w + gs[2]*v2.w + gs[3]*v3.w;
    __stcs(pout, o);

    o.x = gs[4]*v0.x + gs[5]*v1.x + gs[6]*v2.x + gs[7]*v3.x;
    o.y = gs[4]*v0.y + gs[5]*v1.y + gs[6]*v2.y + gs[7]*v3.y;
    o.z = gs[4]*v0.z + gs[5]*v1.z + gs[6]*v2.z + gs[7]*v3.z;
    o.w = gs[4]*v0.w + gs[5]*v1.w + gs[6]*v2.w + gs[7]*v3.w;
    __stcs(pout + BIT_D, o);

    o.x = gs[8]*v0.x + gs[9]*v1.x + gs[10]*v2.x + gs[11]*v3.x;
    o.y = gs[8]*v0.y + gs[9]*v1.y + gs[10]*v2.y + gs[11]*v3.y;
    o.z = gs[8]*v0.z + gs[9]*v1.z + gs[10]*v2.z + gs[11]*v3.z;
    o.w = gs[8]*v0.w + gs[9]*v1.w + gs[10]*v2.w + gs[11]*v3.w;
    __stcs(pout + BIT_C, o);

    o.x = gs[12]*v0.x + gs[13]*v1.x + gs[14]*v2.x + gs[15]*v3.x;
    o.y = gs[12]*v0.y + gs[13]*v1.y + gs[14]*v2.y + gs[15]*v3.y;
    o.z = gs[12]*v0.z + gs[13]*v1.z + gs[14]*v2.z + gs[15]*v3.z;
    o.w = gs[12]*v0.w + gs[13]*v1.w + gs[14]*v2.w + gs[15]*v3.w;
    __stcs(pout + (BIT_C + BIT_D), o);
}

extern "C" void kernel_launch(void* const* d_in, const int* in_sizes, int n_in,
                              void* d_out, int out_size)
{
    const float4* state = (const float4*)d_in[0];
    const float*  gate  = (const float*)d_in[1];
    float4*       out   = (float4*)d_out;

    const unsigned threads = 256;
    const unsigned blocks  = N_REST / threads;   // 2^22 / 256 = 16384
    quantum_gate2_kernel<<<blocks, threads>>>(state, gate, out);
}

// round 6
// speedup vs baseline: 1.0288x; 1.0019x over previous
#include <cuda_runtime.h>

// 2-qubit dense gate on 24-qubit state, batch=4 (innermost, contiguous).
// Flat float index = qindex * 4 + b.  qubit k -> bit (23-k) of qindex.
// support (5,12) -> qindex bits 18 and 11.
//
// R6 = R5 (32 regs, smem gate, occ 81%, store-as-computed) + evict-first
// loads (__ldcs). Input lines are dead after one read; keep them from
// displacing L2 write-coalescing state. Single-variable test on top of
// the best-known config to confirm the ~6.4 TB/s LTS/turnaround ceiling.

static constexpr unsigned REST_BITS = 22;          // 24 - 2 support qubits
static constexpr unsigned N_REST    = 1u << REST_BITS;
static constexpr unsigned BIT_C     = 1u << 18;    // qubit 5
static constexpr unsigned BIT_D     = 1u << 11;    // qubit 12

__global__ void __launch_bounds__(256, 8)
quantum_gate2_kernel(const float4* __restrict__ in,
                     const float*  __restrict__ gate,
                     float4*       __restrict__ out)
{
    __shared__ float gs[16];
    if (threadIdx.x < 16) gs[threadIdx.x] = gate[threadIdx.x];
    __syncthreads();

    const unsigned r = blockIdx.x * blockDim.x + threadIdx.x;
    // Expand rest index: insert zero bits at qindex positions 11 and 18.
    const unsigned low = r & 0x7FFu;           // bits 0..10
    const unsigned mid = (r >> 11) & 0x3Fu;    // -> qindex bits 12..17
    const unsigned hi  = r >> 17;              // -> qindex bits 19..23
    const unsigned qb  = low | (mid << 12) | (hi << 19);

    const float4* pin  = in  + qb;
    float4*       pout = out + qb;

    // Front-batch the 4 independent 16B loads (per-thread MLP=4),
    // evict-first: these lines are never touched again.
    const float4 v0 = __ldcs(pin);                    // c=0,d=0
    const float4 v1 = __ldcs(pin + BIT_D);            // c=0,d=1
    const float4 v2 = __ldcs(pin + BIT_C);            // c=1,d=0
    const float4 v3 = __ldcs(pin + (BIT_C + BIT_D));  // c=1,d=1

    float4 o;

    o.x = gs[0]*v0.x + gs[1]*v1.x + gs[2]*v2.x + gs[3]*v3.x;
    o.y = gs[0]*v0.y + gs[1]*v1.y + gs[2]*v2.y + gs[3]*v3.y;
    o.z = gs[0]*v0.z + gs[1]*v1.z + gs[2]*v2.z + gs[3]*v3.z;
    o.w = gs[0]*v0.w + gs[1]*v1.w + gs[2]*v2.w + gs[3]*v3.w;
    __stcs(pout, o);

    o.x = gs[4]*v0.x + gs[5]*v1.x + gs[6]*v2.x + gs[7]*v3.x;
    o.y = gs[4]*v0.y + gs[5]*v1.y + gs[6]*v2.y + gs[7]*v3.y;
    o.z = gs[4]*v0.z + gs[5]*v1.z + gs[6]*v2.z + gs[7]*v3.z;
    o.w = gs[4]*v0.w + gs[5]*v1.w + gs[6]*v2.w + gs[7]*v3.w;
    __stcs(pout + BIT_D, o);

    o.x = gs[8]*v0.x + gs[9]*v1.x + gs[10]*v2.x + gs[11]*v3.x;
    o.y = gs[8]*v0.y + gs[9]*v1.y + gs[10]*v2.y + gs[11]*v3.y;
    o.z = gs[8]*v0.z + gs[9]*v1.z + gs[10]*v2.z + gs[11]*v3.z;
    o.w = gs[8]*v0.w + gs[9]*v1.w + gs[10]*v2.w + gs[11]*v3.w;
    __stcs(pout + BIT_C, o);

    o.x = gs[12]*v0.x + gs[13]*v1.x + gs[14]*v2.x + gs[15]*v3.x;
    o.y = gs[12]*v0.y + gs[13]*v1.y + gs[14]*v2.y + gs[15]*v3.y;
    o.z = gs[12]*v0.z + gs[13]*v1.z + gs[14]*v2.z + gs[15]*v3.z;
    o.w = gs[12]*v0.w + gs[13]*v1.w + gs[14]*v2.w + gs[15]*v3.w;
    __stcs(pout + (BIT_C + BIT_D), o);
}

extern "C" void kernel_launch(void* const* d_in, const int* in_sizes, int n_in,
                              void* d_out, int out_size)
{
    const float4* state = (const float4*)d_in[0];
    const float*  gate  = (const float*)d_in[1];
    float4*       out   = (float4*)d_out;

    const unsigned threads = 256;
    const unsigned blocks  = N_REST / threads;   // 2^22 / 256 = 16384
    quantum_gate2_kernel<<<blocks, threads>>>(state, gate, out);
}